// round 2
// baseline (speedup 1.0000x reference)
#include <cuda_runtime.h>
#include <math.h>

// Problem constants (fixed by the dataset)
#define B_    512
#define C_    3
#define HH    256
#define WW    256
#define DIN   9216      // 3 patches * 3 ch * 32*32
#define HG_   1024
#define HL_   128
#define HO    1152      // HG + HL

// Scratch (device globals: no allocation allowed)
__device__ float g_glimpse[(size_t)B_ * DIN];   // ~18.9 MB
__device__ float g_h[(size_t)B_ * HG_];         // 2 MB
__device__ float g_hw[(size_t)B_ * HL_];        // 0.25 MB

// ---------------------------------------------------------------------------
// Foveation: one block per batch sample. Builds glimpse row of 9216 floats:
// [patch0 (3x32x32)] [patch1 pooled2 (3x32x32)] [patch2 pooled4 (3x32x32)]
// ---------------------------------------------------------------------------
__global__ void foveate_kernel(const float* __restrict__ x,
                               const float* __restrict__ l) {
    int b = blockIdx.x;
    float l0 = l[2 * b + 0];
    float l1 = l[2 * b + 1];
    // coords = floor(0.5 * ((l + 1) * [H, W])); fx=coords[:,0], fy=coords[:,1]
    // slice start = (y0, x0) = (fy, fx). Same op order as JAX (no FMA fusion risk).
    int x0 = (int)floorf(0.5f * ((l0 + 1.0f) * 256.0f));
    int y0 = (int)floorf(0.5f * ((l1 + 1.0f) * 256.0f));
    // dynamic_slice clamps start to [0, (H+2*pad) - size] = [0, 256]
    x0 = min(max(x0, 0), 256);
    y0 = min(max(y0, 0), 256);

    const float* xb = x + (size_t)b * C_ * HH * WW;
    float* gb = g_glimpse + (size_t)b * DIN;
    int tid = threadIdx.x;

    // patch 0: 32x32, orig row = y0 + i - 16
    for (int idx = tid; idx < 3072; idx += blockDim.x) {
        int c = idx >> 10, q = idx & 1023, i = q >> 5, j = q & 31;
        int r = y0 + i - 16, cc = x0 + j - 16;
        float v = 0.0f;
        if ((unsigned)r < 256u && (unsigned)cc < 256u)
            v = xb[c * 65536 + r * 256 + cc];
        gb[idx] = v;
    }
    // patch 1: 64x64 -> 2x2 mean pool, orig row = y0 + 2*oi + dr - 32
    for (int idx = tid; idx < 3072; idx += blockDim.x) {
        int c = idx >> 10, q = idx & 1023, i = q >> 5, j = q & 31;
        int r0 = y0 + 2 * i - 32, c0 = x0 + 2 * j - 32;
        float s = 0.0f;
#pragma unroll
        for (int dr = 0; dr < 2; ++dr) {
            int r = r0 + dr;
            if ((unsigned)r < 256u) {
#pragma unroll
                for (int dc = 0; dc < 2; ++dc) {
                    int cc = c0 + dc;
                    if ((unsigned)cc < 256u) s += xb[c * 65536 + r * 256 + cc];
                }
            }
        }
        gb[3072 + idx] = s * 0.25f;
    }
    // patch 2: 128x128 -> 4x4 mean pool, orig row = y0 + 4*oi + dr - 64
    for (int idx = tid; idx < 3072; idx += blockDim.x) {
        int c = idx >> 10, q = idx & 1023, i = q >> 5, j = q & 31;
        int r0 = y0 + 4 * i - 64, c0 = x0 + 4 * j - 64;
        float s = 0.0f;
#pragma unroll
        for (int dr = 0; dr < 4; ++dr) {
            int r = r0 + dr;
            if ((unsigned)r < 256u) {
#pragma unroll
                for (int dc = 0; dc < 4; ++dc) {
                    int cc = c0 + dc;
                    if ((unsigned)cc < 256u) s += xb[c * 65536 + r * 256 + cc];
                }
            }
        }
        gb[6144 + idx] = s * 0.0625f;
    }
}

// ---------------------------------------------------------------------------
// hw = relu(l @ W2^T + b2)  : (512,2) x (128,2)^T -> (512,128)
// ---------------------------------------------------------------------------
__global__ void where_kernel(const float* __restrict__ l,
                             const float* __restrict__ W2,
                             const float* __restrict__ b2) {
    int idx = blockIdx.x * blockDim.x + threadIdx.x;
    if (idx >= B_ * HL_) return;
    int b = idx >> 7, o = idx & 127;
    float v = b2[o] + l[2 * b] * W2[2 * o] + l[2 * b + 1] * W2[2 * o + 1];
    g_hw[idx] = fmaxf(v, 0.0f);
}

// ---------------------------------------------------------------------------
// Tiled NT GEMM core: A [M x K] row-major, Bw [N x K] row-major (weights).
// 64x64 tile, BK=16, 256 threads, 4x4 per thread, reg->smem prefetch pipeline.
// Requires K % 16 == 0, m0/n0 tiles fully in-bounds (all dims here divide).
// ---------------------------------------------------------------------------
__device__ __forceinline__ void gemm_accum(const float* __restrict__ A,
                                           const float* __restrict__ Bw,
                                           int K, int m0, int n0,
                                           float (&acc)[4][4],
                                           float (*As)[68], float (*Bs)[68]) {
    int tid = threadIdx.x;
    int tx = tid & 15, ty = tid >> 4;
    int lrow = tid >> 2;            // 0..63
    int lk = (tid & 3) << 2;        // 0,4,8,12

    const float* Ap = A + (size_t)(m0 + lrow) * K + lk;
    const float* Bp = Bw + (size_t)(n0 + lrow) * K + lk;
    int nt = K >> 4;

    float4 ar = *(const float4*)Ap;
    float4 br = *(const float4*)Bp;

    for (int t = 0; t < nt; ++t) {
        // transpose-store into k-major smem (padded stride 68 -> <=2-way conflicts)
        As[lk + 0][lrow] = ar.x; As[lk + 1][lrow] = ar.y;
        As[lk + 2][lrow] = ar.z; As[lk + 3][lrow] = ar.w;
        Bs[lk + 0][lrow] = br.x; Bs[lk + 1][lrow] = br.y;
        Bs[lk + 2][lrow] = br.z; Bs[lk + 3][lrow] = br.w;
        __syncthreads();
        if (t + 1 < nt) {
            ar = *(const float4*)(Ap + (t + 1) * 16);
            br = *(const float4*)(Bp + (t + 1) * 16);
        }
#pragma unroll
        for (int k = 0; k < 16; ++k) {
            float4 av = *(const float4*)&As[k][ty << 2];
            float4 bv = *(const float4*)&Bs[k][tx << 2];
            float a[4] = {av.x, av.y, av.z, av.w};
            float bb[4] = {bv.x, bv.y, bv.z, bv.w};
#pragma unroll
            for (int i = 0; i < 4; ++i)
#pragma unroll
                for (int j = 0; j < 4; ++j)
                    acc[i][j] = fmaf(a[i], bb[j], acc[i][j]);
        }
        __syncthreads();
    }
}

// h = relu(glimpse @ W1^T + b1) : (512,9216) x (1024,9216)^T -> (512,1024)
__global__ void __launch_bounds__(256) gemm1_kernel(const float* __restrict__ W1,
                                                    const float* __restrict__ b1) {
    __shared__ __align__(16) float As[16][68];
    __shared__ __align__(16) float Bs[16][68];
    float acc[4][4] = {};
    int m0 = blockIdx.y * 64, n0 = blockIdx.x * 64;
    gemm_accum(g_glimpse, W1, DIN, m0, n0, acc, As, Bs);

    int tid = threadIdx.x, tx = tid & 15, ty = tid >> 4;
#pragma unroll
    for (int i = 0; i < 4; ++i) {
        int m = m0 + (ty << 2) + i;
#pragma unroll
        for (int j = 0; j < 4; ++j) {
            int n = n0 + (tx << 2) + j;
            float v = acc[i][j] + b1[n];
            g_h[(size_t)m * HG_ + n] = fmaxf(v, 0.0f);
        }
    }
}

// out = relu(h @ W3^T + b3 + hw @ W4^T + b4) : (512,1152)
__global__ void __launch_bounds__(256) gemm2_kernel(const float* __restrict__ W3,
                                                    const float* __restrict__ b3,
                                                    const float* __restrict__ W4,
                                                    const float* __restrict__ b4,
                                                    float* __restrict__ out) {
    __shared__ __align__(16) float As[16][68];
    __shared__ __align__(16) float Bs[16][68];
    float acc[4][4] = {};
    int m0 = blockIdx.y * 64, n0 = blockIdx.x * 64;
    gemm_accum(g_h, W3, HG_, m0, n0, acc, As, Bs);
    gemm_accum(g_hw, W4, HL_, m0, n0, acc, As, Bs);

    int tid = threadIdx.x, tx = tid & 15, ty = tid >> 4;
#pragma unroll
    for (int i = 0; i < 4; ++i) {
        int m = m0 + (ty << 2) + i;
#pragma unroll
        for (int j = 0; j < 4; ++j) {
            int n = n0 + (tx << 2) + j;
            float v = acc[i][j] + b3[n] + b4[n];
            out[(size_t)m * HO + n] = fmaxf(v, 0.0f);
        }
    }
}

// ---------------------------------------------------------------------------
extern "C" void kernel_launch(void* const* d_in, const int* in_sizes, int n_in,
                              void* d_out, int out_size) {
    const float* x  = (const float*)d_in[0];
    const float* l  = (const float*)d_in[1];
    const float* W1 = (const float*)d_in[2];
    const float* b1 = (const float*)d_in[3];
    const float* W2 = (const float*)d_in[4];
    const float* b2 = (const float*)d_in[5];
    const float* W3 = (const float*)d_in[6];
    const float* b3 = (const float*)d_in[7];
    const float* W4 = (const float*)d_in[8];
    const float* b4 = (const float*)d_in[9];
    float* out = (float*)d_out;

    foveate_kernel<<<B_, 256>>>(x, l);
    where_kernel<<<(B_ * HL_ + 255) / 256, 256>>>(l, W2, b2);
    gemm1_kernel<<<dim3(HG_ / 64, B_ / 64), 256>>>(W1, b1);
    gemm2_kernel<<<dim3(HO / 64, B_ / 64), 256>>>(W3, b3, W4, b4, out);
}

// round 8
// speedup vs baseline: 1.7758x; 1.7758x over previous
#include <cuda_runtime.h>
#include <cuda_fp16.h>
#include <cstdint>
#include <math.h>

#define B_    512
#define C_    3
#define DIN   9216
#define HG_   1024
#define HL_   128
#define HO    1152

// ---------------- scratch (device globals; no allocation allowed) -----------
__device__ __align__(256) __half g_Ahi[(size_t)B_ * DIN];
__device__ __align__(256) __half g_Alo[(size_t)B_ * DIN];
__device__ __align__(256) __half g_W1hi[(size_t)HG_ * DIN];
__device__ __align__(256) __half g_W1lo[(size_t)HG_ * DIN];
__device__ __align__(256) __half g_acthi[(size_t)B_ * HO];
__device__ __align__(256) __half g_actlo[(size_t)B_ * HO];
__device__ __align__(256) __half g_W34hi[(size_t)HO * HO];
__device__ __align__(256) __half g_W34lo[(size_t)HO * HO];

// ---------------- helpers ----------------------------------------------------
__device__ __forceinline__ uint32_t smem_u32(const void* p) {
    uint32_t a;
    asm("{ .reg .u64 t; cvta.to.shared.u64 t, %1; cvt.u32.u64 %0, t; }" : "=r"(a) : "l"(p));
    return a;
}
__device__ __forceinline__ void split_h(float v, __half& h, __half& l) {
    h = __float2half_rn(v);
    l = __float2half_rn(v - __half2float(h));
}
__device__ __forceinline__ void ldsm_x4(uint32_t (&f)[4], uint32_t addr) {
    asm volatile("ldmatrix.sync.aligned.m8n8.x4.shared.b16 {%0,%1,%2,%3}, [%4];"
                 : "=r"(f[0]), "=r"(f[1]), "=r"(f[2]), "=r"(f[3]) : "r"(addr));
}
__device__ __forceinline__ void mma16816(float (&c)[4], const uint32_t (&a)[4],
                                         uint32_t b0, uint32_t b1) {
    asm volatile("mma.sync.aligned.m16n8k16.row.col.f32.f16.f16.f32 "
                 "{%0,%1,%2,%3}, {%4,%5,%6,%7}, {%8,%9}, {%0,%1,%2,%3};"
                 : "+f"(c[0]), "+f"(c[1]), "+f"(c[2]), "+f"(c[3])
                 : "r"(a[0]), "r"(a[1]), "r"(a[2]), "r"(a[3]), "r"(b0), "r"(b1));
}

// ---------------- foveation: emits fp16 hi/lo glimpse rows -------------------
__global__ void foveate_kernel(const float* __restrict__ x,
                               const float* __restrict__ l,
                               __half* __restrict__ ghi, __half* __restrict__ glo) {
    int b = blockIdx.x;
    float l0 = l[2 * b + 0];
    float l1 = l[2 * b + 1];
    int x0 = (int)floorf(0.5f * ((l0 + 1.0f) * 256.0f));
    int y0 = (int)floorf(0.5f * ((l1 + 1.0f) * 256.0f));
    x0 = min(max(x0, 0), 256);
    y0 = min(max(y0, 0), 256);

    const float* xb = x + (size_t)b * C_ * 256 * 256;
    __half* gh = ghi + (size_t)b * DIN;
    __half* gl = glo + (size_t)b * DIN;
    int tid = threadIdx.x;

    for (int idx = tid; idx < 3072; idx += blockDim.x) {
        int c = idx >> 10, q = idx & 1023, i = q >> 5, j = q & 31;
        int r = y0 + i - 16, cc = x0 + j - 16;
        float v = 0.0f;
        if ((unsigned)r < 256u && (unsigned)cc < 256u)
            v = xb[c * 65536 + r * 256 + cc];
        split_h(v, gh[idx], gl[idx]);
    }
    for (int idx = tid; idx < 3072; idx += blockDim.x) {
        int c = idx >> 10, q = idx & 1023, i = q >> 5, j = q & 31;
        int r0 = y0 + 2 * i - 32, c0 = x0 + 2 * j - 32;
        float s = 0.0f;
#pragma unroll
        for (int dr = 0; dr < 2; ++dr) {
            int r = r0 + dr;
            if ((unsigned)r < 256u)
#pragma unroll
                for (int dc = 0; dc < 2; ++dc) {
                    int cc = c0 + dc;
                    if ((unsigned)cc < 256u) s += xb[c * 65536 + r * 256 + cc];
                }
        }
        split_h(s * 0.25f, gh[3072 + idx], gl[3072 + idx]);
    }
    for (int idx = tid; idx < 3072; idx += blockDim.x) {
        int c = idx >> 10, q = idx & 1023, i = q >> 5, j = q & 31;
        int r0 = y0 + 4 * i - 64, c0 = x0 + 4 * j - 64;
        float s = 0.0f;
#pragma unroll
        for (int dr = 0; dr < 4; ++dr) {
            int r = r0 + dr;
            if ((unsigned)r < 256u)
#pragma unroll
                for (int dc = 0; dc < 4; ++dc) {
                    int cc = c0 + dc;
                    if ((unsigned)cc < 256u) s += xb[c * 65536 + r * 256 + cc];
                }
        }
        split_h(s * 0.0625f, gh[6144 + idx], gl[6144 + idx]);
    }
}

// ---------------- fp32 -> fp16 hi/lo converters ------------------------------
__global__ void conv_split4(const float* __restrict__ W,
                            __half* __restrict__ hi, __half* __restrict__ lo, int n4) {
    int i = blockIdx.x * blockDim.x + threadIdx.x;
    if (i >= n4) return;
    float4 v = ((const float4*)W)[i];
    union U { __half h[4]; uint2 u; } uh, ul;
    split_h(v.x, uh.h[0], ul.h[0]);
    split_h(v.y, uh.h[1], ul.h[1]);
    split_h(v.z, uh.h[2], ul.h[2]);
    split_h(v.w, uh.h[3], ul.h[3]);
    ((uint2*)hi)[i] = uh.u;
    ((uint2*)lo)[i] = ul.u;
}

__global__ void conv_w34(const float* __restrict__ W3, const float* __restrict__ W4,
                         __half* __restrict__ hi, __half* __restrict__ lo) {
    int idx = blockIdx.x * blockDim.x + threadIdx.x;
    if (idx >= HO * HO) return;
    int n = idx / HO, k = idx - n * HO;
    float w = (k < HG_) ? W3[(size_t)n * HG_ + k] : W4[(size_t)n * HL_ + (k - HG_)];
    split_h(w, hi[idx], lo[idx]);
}

// ---------------- hw = relu(l@W2^T + b2) -> act cols [1024,1152) -------------
__global__ void where_kernel(const float* __restrict__ l,
                             const float* __restrict__ W2,
                             const float* __restrict__ b2,
                             __half* __restrict__ acthi, __half* __restrict__ actlo) {
    int idx = blockIdx.x * blockDim.x + threadIdx.x;
    if (idx >= B_ * HL_) return;
    int b = idx >> 7, o = idx & 127;
    float v = b2[o] + l[2 * b] * W2[2 * o] + l[2 * b + 1] * W2[2 * o + 1];
    v = fmaxf(v, 0.0f);
    split_h(v, acthi[(size_t)b * HO + HG_ + o], actlo[(size_t)b * HO + HG_ + o]);
}

// ---------------- HMMA GEMM: D = A@B^T, 3-pass fp16 hi/lo split --------------
// 64x64 CTA tile, BK=64, 3-stage cp.async, 8 warps (warp tile 32x16).
#define STG_BYTES 16384           // (64+64) rows * 128B
#define GEMM_SMEM (3 * STG_BYTES)

// issue one 64x64x64 tile's cp.asyncs into 'stage'
__device__ __forceinline__ void load_tile(uint32_t sb, int stage, int t, int KTP,
                                          const __half* __restrict__ Ah,
                                          const __half* __restrict__ Al,
                                          const __half* __restrict__ Bh,
                                          const __half* __restrict__ Bl,
                                          int m0, int n0, int K) {
    int p = 0, kk = t;
    if (kk >= KTP) { p = 1; kk -= KTP; }
    if (kk >= KTP) { p = 2; kk -= KTP; }
    const __half* As = (p == 1) ? Al : Ah;
    const __half* Bs = (p == 2) ? Bl : Bh;
    int k0 = kk * 64;
    uint32_t base = sb + stage * STG_BYTES;
    int tid = threadIdx.x;
#pragma unroll
    for (int i = 0; i < 4; ++i) {
        int cid = i * 256 + tid;            // 0..1023 chunks of 16B
        int isB = cid >> 9;
        int rem = cid & 511;
        int row = rem >> 3, c = rem & 7;
        const __half* src = isB ? (Bs + (size_t)(n0 + row) * K + k0 + c * 8)
                                : (As + (size_t)(m0 + row) * K + k0 + c * 8);
        uint32_t dst = base + isB * 8192 + row * 128 + ((c ^ (row & 7)) << 4);
        asm volatile("cp.async.cg.shared.global [%0], [%1], 16;" :: "r"(dst), "l"(src) : "memory");
    }
    asm volatile("cp.async.commit_group;" ::: "memory");
}

// EPI 1: act = relu(acc + bias1), split to acthi/actlo (stride HO)
// EPI 2: out = relu(acc + bias1 + bias2), f32 (stride Ntot)
template <int EPI>
__global__ void __launch_bounds__(256, 1)
gemm_hmma(const __half* __restrict__ Ah, const __half* __restrict__ Al,
          const __half* __restrict__ Bh, const __half* __restrict__ Bl,
          int K, int KTP, int Ntot,
          const float* __restrict__ bias1, const float* __restrict__ bias2,
          float* __restrict__ outf, __half* __restrict__ acth, __half* __restrict__ actl) {
    extern __shared__ char smem[];
    uint32_t sb = smem_u32(smem);
    int tid = threadIdx.x, lane = tid & 31, w = tid >> 5;
    int wm = w & 1, wn = w >> 1;        // 2 x 4 warp grid, warp tile 32x16
    int m0 = blockIdx.y * 64, n0 = blockIdx.x * 64;
    int T = 3 * KTP;

    // ldmatrix lane addressing: r = lane&7, sel = lane>>3
    int lr = lane & 7;
    int rsel = (lane >> 3) & 1;          // +8 rows
    int csel = lane >> 4;                // +1 chunk (k hi 8)

    load_tile(sb, 0, 0, KTP, Ah, Al, Bh, Bl, m0, n0, K);
    load_tile(sb, 1, 1, KTP, Ah, Al, Bh, Bl, m0, n0, K);

    float acc[2][2][4] = {};

    for (int t = 0; t < T; ++t) {
        asm volatile("cp.async.wait_group 1;" ::: "memory");
        __syncthreads();
        if (t + 2 < T)
            load_tile(sb, (t + 2) % 3, t + 2, KTP, Ah, Al, Bh, Bl, m0, n0, K);
        else
            asm volatile("cp.async.commit_group;" ::: "memory");

        uint32_t stA = sb + (t % 3) * STG_BYTES;
        uint32_t stB = stA + 8192;
#pragma unroll
        for (int s = 0; s < 4; ++s) {
            int chunk = 2 * s + csel;
            uint32_t aF[2][4], bF[4];
#pragma unroll
            for (int mi = 0; mi < 2; ++mi) {
                int row = wm * 32 + mi * 16 + lr + rsel * 8;
                ldsm_x4(aF[mi], stA + row * 128 + ((chunk ^ (row & 7)) << 4));
            }
            {
                int row = wn * 16 + lr + rsel * 8;
                ldsm_x4(bF, stB + row * 128 + ((chunk ^ (row & 7)) << 4));
            }
#pragma unroll
            for (int mi = 0; mi < 2; ++mi) {
                mma16816(acc[mi][0], aF[mi], bF[0], bF[2]);
                mma16816(acc[mi][1], aF[mi], bF[1], bF[3]);
            }
        }
        __syncthreads();
    }

    // epilogue
    int r = lane >> 2, c2 = (lane & 3) * 2;
#pragma unroll
    for (int mi = 0; mi < 2; ++mi) {
#pragma unroll
        for (int ni = 0; ni < 2; ++ni) {
            int mA = m0 + wm * 32 + mi * 16 + r;
            int mB = mA + 8;
            int n = n0 + wn * 16 + ni * 8 + c2;
            float* a = acc[mi][ni];
            if (EPI == 1) {
                float bb0 = bias1[n], bb1 = bias1[n + 1];
                float v0 = fmaxf(a[0] + bb0, 0.0f), v1 = fmaxf(a[1] + bb1, 0.0f);
                float v2 = fmaxf(a[2] + bb0, 0.0f), v3 = fmaxf(a[3] + bb1, 0.0f);
                __half h0, h1, h2, h3, l0, l1, l2, l3;
                split_h(v0, h0, l0); split_h(v1, h1, l1);
                split_h(v2, h2, l2); split_h(v3, h3, l3);
                *(__half2*)(acth + (size_t)mA * HO + n) = __halves2half2(h0, h1);
                *(__half2*)(actl + (size_t)mA * HO + n) = __halves2half2(l0, l1);
                *(__half2*)(acth + (size_t)mB * HO + n) = __halves2half2(h2, h3);
                *(__half2*)(actl + (size_t)mB * HO + n) = __halves2half2(l2, l3);
            } else {
                float bb0 = bias1[n] + bias2[n];
                float bb1 = bias1[n + 1] + bias2[n + 1];
                float2 o0 = make_float2(fmaxf(a[0] + bb0, 0.0f), fmaxf(a[1] + bb1, 0.0f));
                float2 o1 = make_float2(fmaxf(a[2] + bb0, 0.0f), fmaxf(a[3] + bb1, 0.0f));
                *(float2*)(outf + (size_t)mA * Ntot + n) = o0;
                *(float2*)(outf + (size_t)mB * Ntot + n) = o1;
            }
        }
    }
}

// ---------------------------------------------------------------------------
extern "C" void kernel_launch(void* const* d_in, const int* in_sizes, int n_in,
                              void* d_out, int out_size) {
    const float* x  = (const float*)d_in[0];
    const float* l  = (const float*)d_in[1];
    const float* W1 = (const float*)d_in[2];
    const float* b1 = (const float*)d_in[3];
    const float* W2 = (const float*)d_in[4];
    const float* b2 = (const float*)d_in[5];
    const float* W3 = (const float*)d_in[6];
    const float* b3 = (const float*)d_in[7];
    const float* W4 = (const float*)d_in[8];
    const float* b4 = (const float*)d_in[9];
    float* out = (float*)d_out;

    void *pAhi, *pAlo, *pW1hi, *pW1lo, *pActhi, *pActlo, *pW34hi, *pW34lo;
    cudaGetSymbolAddress(&pAhi, g_Ahi);
    cudaGetSymbolAddress(&pAlo, g_Alo);
    cudaGetSymbolAddress(&pW1hi, g_W1hi);
    cudaGetSymbolAddress(&pW1lo, g_W1lo);
    cudaGetSymbolAddress(&pActhi, g_acthi);
    cudaGetSymbolAddress(&pActlo, g_actlo);
    cudaGetSymbolAddress(&pW34hi, g_W34hi);
    cudaGetSymbolAddress(&pW34lo, g_W34lo);

    cudaFuncSetAttribute(gemm_hmma<1>, cudaFuncAttributeMaxDynamicSharedMemorySize, GEMM_SMEM);
    cudaFuncSetAttribute(gemm_hmma<2>, cudaFuncAttributeMaxDynamicSharedMemorySize, GEMM_SMEM);

    foveate_kernel<<<B_, 256>>>(x, l, (__half*)pAhi, (__half*)pAlo);

    int n4 = HG_ * DIN / 4;
    conv_split4<<<(n4 + 255) / 256, 256>>>(W1, (__half*)pW1hi, (__half*)pW1lo, n4);
    conv_w34<<<(HO * HO + 255) / 256, 256>>>(W3, W4, (__half*)pW34hi, (__half*)pW34lo);
    where_kernel<<<(B_ * HL_ + 255) / 256, 256>>>(l, W2, b2, (__half*)pActhi, (__half*)pActlo);

    // GEMM1: (512 x 9216) @ (1024 x 9216)^T -> act[:, 0:1024] (bias+relu+split fused)
    gemm_hmma<1><<<dim3(HG_ / 64, B_ / 64), 256, GEMM_SMEM>>>(
        (const __half*)pAhi, (const __half*)pAlo,
        (const __half*)pW1hi, (const __half*)pW1lo,
        DIN, DIN / 64, HG_, b1, nullptr,
        nullptr, (__half*)pActhi, (__half*)pActlo);

    // GEMM2: (512 x 1152) @ (1152 x 1152)^T -> out (bias3+bias4+relu fused)
    gemm_hmma<2><<<dim3(HO / 64, B_ / 64), 256, GEMM_SMEM>>>(
        (const __half*)pActhi, (const __half*)pActlo,
        (const __half*)pW34hi, (const __half*)pW34lo,
        HO, HO / 64, HO, b3, b4,
        out, nullptr, nullptr);
}

// round 11
// speedup vs baseline: 2.4758x; 1.3942x over previous
#include <cuda_runtime.h>
#include <cuda_fp16.h>
#include <cstdint>
#include <math.h>

#define B_    512
#define C_    3
#define DIN   9216
#define HG_   1024
#define HL_   128
#define HO    1152
#define SPLITK 4

// ---------------- scratch (device globals; no allocation allowed) -----------
__device__ __align__(256) __half g_Ahi[(size_t)B_ * DIN];
__device__ __align__(256) __half g_Alo[(size_t)B_ * DIN];
__device__ __align__(256) __half g_W1hi[(size_t)HG_ * DIN];
__device__ __align__(256) __half g_W1lo[(size_t)HG_ * DIN];
__device__ __align__(256) float  g_part[(size_t)SPLITK * B_ * HG_];
__device__ __align__(256) __half g_acthi[(size_t)B_ * HO];
__device__ __align__(256) __half g_actlo[(size_t)B_ * HO];
__device__ __align__(256) __half g_W34hi[(size_t)HO * HO];
__device__ __align__(256) __half g_W34lo[(size_t)HO * HO];

// ---------------- helpers ----------------------------------------------------
__device__ __forceinline__ uint32_t smem_u32(const void* p) {
    uint32_t a;
    asm("{ .reg .u64 t; cvta.to.shared.u64 t, %1; cvt.u32.u64 %0, t; }" : "=r"(a) : "l"(p));
    return a;
}
__device__ __forceinline__ void split_h(float v, __half& h, __half& l) {
    h = __float2half_rn(v);
    l = __float2half_rn(v - __half2float(h));
}
__device__ __forceinline__ void ldsm_x4(uint32_t (&f)[4], uint32_t addr) {
    asm volatile("ldmatrix.sync.aligned.m8n8.x4.shared.b16 {%0,%1,%2,%3}, [%4];"
                 : "=r"(f[0]), "=r"(f[1]), "=r"(f[2]), "=r"(f[3]) : "r"(addr));
}
__device__ __forceinline__ void mma16816(float (&c)[4], const uint32_t (&a)[4],
                                         uint32_t b0, uint32_t b1) {
    asm volatile("mma.sync.aligned.m16n8k16.row.col.f32.f16.f16.f32 "
                 "{%0,%1,%2,%3}, {%4,%5,%6,%7}, {%8,%9}, {%0,%1,%2,%3};"
                 : "+f"(c[0]), "+f"(c[1]), "+f"(c[2]), "+f"(c[3])
                 : "r"(a[0]), "r"(a[1]), "r"(a[2]), "r"(a[3]), "r"(b0), "r"(b1));
}

// ---------------- foveation: emits fp16 hi/lo glimpse rows -------------------
__global__ void foveate_kernel(const float* __restrict__ x,
                               const float* __restrict__ l,
                               __half* __restrict__ ghi, __half* __restrict__ glo) {
    int b = blockIdx.x;
    float l0 = l[2 * b + 0];
    float l1 = l[2 * b + 1];
    int x0 = (int)floorf(0.5f * ((l0 + 1.0f) * 256.0f));
    int y0 = (int)floorf(0.5f * ((l1 + 1.0f) * 256.0f));
    x0 = min(max(x0, 0), 256);
    y0 = min(max(y0, 0), 256);

    const float* xb = x + (size_t)b * C_ * 256 * 256;
    __half* gh = ghi + (size_t)b * DIN;
    __half* gl = glo + (size_t)b * DIN;
    int tid = threadIdx.x;

    for (int idx = tid; idx < 3072; idx += blockDim.x) {
        int c = idx >> 10, q = idx & 1023, i = q >> 5, j = q & 31;
        int r = y0 + i - 16, cc = x0 + j - 16;
        float v = 0.0f;
        if ((unsigned)r < 256u && (unsigned)cc < 256u)
            v = xb[c * 65536 + r * 256 + cc];
        split_h(v, gh[idx], gl[idx]);
    }
    for (int idx = tid; idx < 3072; idx += blockDim.x) {
        int c = idx >> 10, q = idx & 1023, i = q >> 5, j = q & 31;
        int r0 = y0 + 2 * i - 32, c0 = x0 + 2 * j - 32;
        float s = 0.0f;
#pragma unroll
        for (int dr = 0; dr < 2; ++dr) {
            int r = r0 + dr;
            if ((unsigned)r < 256u)
#pragma unroll
                for (int dc = 0; dc < 2; ++dc) {
                    int cc = c0 + dc;
                    if ((unsigned)cc < 256u) s += xb[c * 65536 + r * 256 + cc];
                }
        }
        split_h(s * 0.25f, gh[3072 + idx], gl[3072 + idx]);
    }
    for (int idx = tid; idx < 3072; idx += blockDim.x) {
        int c = idx >> 10, q = idx & 1023, i = q >> 5, j = q & 31;
        int r0 = y0 + 4 * i - 64, c0 = x0 + 4 * j - 64;
        float s = 0.0f;
#pragma unroll
        for (int dr = 0; dr < 4; ++dr) {
            int r = r0 + dr;
            if ((unsigned)r < 256u)
#pragma unroll
                for (int dc = 0; dc < 4; ++dc) {
                    int cc = c0 + dc;
                    if ((unsigned)cc < 256u) s += xb[c * 65536 + r * 256 + cc];
                }
        }
        split_h(s * 0.0625f, gh[6144 + idx], gl[6144 + idx]);
    }
}

// ---------------- fp32 -> fp16 hi/lo converters ------------------------------
__global__ void conv_split4(const float* __restrict__ W,
                            __half* __restrict__ hi, __half* __restrict__ lo, int n4) {
    int i = blockIdx.x * blockDim.x + threadIdx.x;
    if (i >= n4) return;
    float4 v = ((const float4*)W)[i];
    union U { __half h[4]; uint2 u; } uh, ul;
    split_h(v.x, uh.h[0], ul.h[0]);
    split_h(v.y, uh.h[1], ul.h[1]);
    split_h(v.z, uh.h[2], ul.h[2]);
    split_h(v.w, uh.h[3], ul.h[3]);
    ((uint2*)hi)[i] = uh.u;
    ((uint2*)lo)[i] = ul.u;
}

__global__ void conv_w34(const float* __restrict__ W3, const float* __restrict__ W4,
                         __half* __restrict__ hi, __half* __restrict__ lo) {
    int idx = blockIdx.x * blockDim.x + threadIdx.x;
    if (idx >= HO * HO) return;
    int n = idx / HO, k = idx - n * HO;
    float w = (k < HG_) ? W3[(size_t)n * HG_ + k] : W4[(size_t)n * HL_ + (k - HG_)];
    split_h(w, hi[idx], lo[idx]);
}

// ---------------- hw = relu(l@W2^T + b2) -> act cols [1024,1152) -------------
__global__ void where_kernel(const float* __restrict__ l,
                             const float* __restrict__ W2,
                             const float* __restrict__ b2,
                             __half* __restrict__ acthi, __half* __restrict__ actlo) {
    int idx = blockIdx.x * blockDim.x + threadIdx.x;
    if (idx >= B_ * HL_) return;
    int b = idx >> 7, o = idx & 127;
    float v = b2[o] + l[2 * b] * W2[2 * o] + l[2 * b + 1] * W2[2 * o + 1];
    v = fmaxf(v, 0.0f);
    split_h(v, acthi[(size_t)b * HO + HG_ + o], actlo[(size_t)b * HO + HG_ + o]);
}

// ---------------- split-K reduce + bias + relu + re-split --------------------
__global__ void reduce1_kernel(const float* __restrict__ part,
                               const float* __restrict__ b1,
                               __half* __restrict__ acthi, __half* __restrict__ actlo) {
    int idx = blockIdx.x * blockDim.x + threadIdx.x;
    if (idx >= B_ * HG_) return;
    const int S = B_ * HG_;
    float s = part[idx] + part[idx + S] + part[idx + 2 * S] + part[idx + 3 * S];
    int m = idx >> 10, n = idx & 1023;
    s = fmaxf(s + b1[n], 0.0f);
    __half h, lo;
    split_h(s, h, lo);
    acthi[(size_t)m * HO + n] = h;
    actlo[(size_t)m * HO + n] = lo;
}

// ============================================================================
// GEMM1: 128x128 CTA tile, BK=64, split-K=4, 3-stage cp.async, 8 warps.
// Warp grid 2x4, warp tile 64x32. Partials (no bias) -> g_part[z].
// ============================================================================
#define STG1   32768              // (128+128) rows * 128B
#define SMEM1  (3 * STG1)

__device__ __forceinline__ void load_tile128(uint32_t sb, int stage, int t, int KTP,
                                             const __half* __restrict__ Ah,
                                             const __half* __restrict__ Al,
                                             const __half* __restrict__ Bh,
                                             const __half* __restrict__ Bl,
                                             int m0, int n0, int kbase, int K) {
    int p = 0, kk = t;
    if (kk >= KTP) { p = 1; kk -= KTP; }
    if (kk >= KTP) { p = 2; kk -= KTP; }
    const __half* As = (p == 1) ? Al : Ah;
    const __half* Bs = (p == 2) ? Bl : Bh;
    int k0 = kbase + kk * 64;
    uint32_t base = sb + stage * STG1;
    int tid = threadIdx.x;
#pragma unroll
    for (int i = 0; i < 8; ++i) {
        int cid = i * 256 + tid;            // 0..2047 chunks of 16B
        int isB = cid >> 10;
        int rem = cid & 1023;
        int row = rem >> 3, c = rem & 7;
        const __half* src = isB ? (Bs + (size_t)(n0 + row) * K + k0 + c * 8)
                                : (As + (size_t)(m0 + row) * K + k0 + c * 8);
        uint32_t dst = base + isB * 16384 + row * 128 + ((c ^ (row & 7)) << 4);
        asm volatile("cp.async.cg.shared.global [%0], [%1], 16;" :: "r"(dst), "l"(src) : "memory");
    }
    asm volatile("cp.async.commit_group;" ::: "memory");
}

__global__ void __launch_bounds__(256, 1)
gemm1_128(const __half* __restrict__ Ah, const __half* __restrict__ Al,
          const __half* __restrict__ Bh, const __half* __restrict__ Bl,
          float* __restrict__ part) {
    extern __shared__ char smem[];
    uint32_t sb = smem_u32(smem);
    int tid = threadIdx.x, lane = tid & 31, w = tid >> 5;
    int wm = w & 1, wn = w >> 1;            // 2 x 4 warps; warp tile 64 x 32
    int m0 = blockIdx.y * 128, n0 = blockIdx.x * 128;
    const int KTP = DIN / (SPLITK * 64);    // 36 k-tiles per pass per split
    const int T = 3 * KTP;                  // 108
    int kbase = blockIdx.z * (DIN / SPLITK);
    part += (size_t)blockIdx.z * B_ * HG_;

    int lr = lane & 7;
    int rsel = (lane >> 3) & 1;
    int csel = lane >> 4;

    // precomputed ldsm row offsets (row & 7 == lr for all fragments)
    uint32_t offA[4], offB[2];
#pragma unroll
    for (int mi = 0; mi < 4; ++mi)
        offA[mi] = (uint32_t)(wm * 64 + mi * 16 + lr + rsel * 8) * 128;
#pragma unroll
    for (int bi = 0; bi < 2; ++bi)
        offB[bi] = (uint32_t)(wn * 32 + bi * 16 + lr + rsel * 8) * 128;

    load_tile128(sb, 0, 0, KTP, Ah, Al, Bh, Bl, m0, n0, kbase, DIN);
    load_tile128(sb, 1, 1, KTP, Ah, Al, Bh, Bl, m0, n0, kbase, DIN);

    float acc[4][4][4] = {};

    for (int t = 0; t < T; ++t) {
        asm volatile("cp.async.wait_group 1;" ::: "memory");
        __syncthreads();
        if (t + 2 < T)
            load_tile128(sb, (t + 2) % 3, t + 2, KTP, Ah, Al, Bh, Bl, m0, n0, kbase, DIN);
        else
            asm volatile("cp.async.commit_group;" ::: "memory");

        uint32_t stA = sb + (t % 3) * STG1;
        uint32_t stB = stA + 16384;
#pragma unroll
        for (int s = 0; s < 4; ++s) {
            uint32_t swz = (uint32_t)(((2 * s + csel) ^ lr) << 4);
            uint32_t aF[4][4], bF[2][4];
#pragma unroll
            for (int mi = 0; mi < 4; ++mi)
                ldsm_x4(aF[mi], stA + offA[mi] + swz);
#pragma unroll
            for (int bi = 0; bi < 2; ++bi)
                ldsm_x4(bF[bi], stB + offB[bi] + swz);
#pragma unroll
            for (int mi = 0; mi < 4; ++mi)
#pragma unroll
                for (int j = 0; j < 4; ++j)
                    mma16816(acc[mi][j], aF[mi], bF[j >> 1][j & 1], bF[j >> 1][(j & 1) + 2]);
        }
        __syncthreads();
    }

    // partial store (fp32, no bias)
    int r = lane >> 2, c2 = (lane & 3) * 2;
#pragma unroll
    for (int mi = 0; mi < 4; ++mi) {
#pragma unroll
        for (int j = 0; j < 4; ++j) {
            int mA = m0 + wm * 64 + mi * 16 + r;
            int n = n0 + wn * 32 + j * 8 + c2;
            float* a = acc[mi][j];
            *(float2*)(part + (size_t)mA * HG_ + n) = make_float2(a[0], a[1]);
            *(float2*)(part + (size_t)(mA + 8) * HG_ + n) = make_float2(a[2], a[3]);
        }
    }
}

// ============================================================================
// GEMM2: 64x64 tile HMMA kernel (proven R8 path), bias3+bias4+relu epilogue.
// ============================================================================
#define STG_BYTES 16384
#define GEMM_SMEM (3 * STG_BYTES)

__device__ __forceinline__ void load_tile(uint32_t sb, int stage, int t, int KTP,
                                          const __half* __restrict__ Ah,
                                          const __half* __restrict__ Al,
                                          const __half* __restrict__ Bh,
                                          const __half* __restrict__ Bl,
                                          int m0, int n0, int K) {
    int p = 0, kk = t;
    if (kk >= KTP) { p = 1; kk -= KTP; }
    if (kk >= KTP) { p = 2; kk -= KTP; }
    const __half* As = (p == 1) ? Al : Ah;
    const __half* Bs = (p == 2) ? Bl : Bh;
    int k0 = kk * 64;
    uint32_t base = sb + stage * STG_BYTES;
    int tid = threadIdx.x;
#pragma unroll
    for (int i = 0; i < 4; ++i) {
        int cid = i * 256 + tid;
        int isB = cid >> 9;
        int rem = cid & 511;
        int row = rem >> 3, c = rem & 7;
        const __half* src = isB ? (Bs + (size_t)(n0 + row) * K + k0 + c * 8)
                                : (As + (size_t)(m0 + row) * K + k0 + c * 8);
        uint32_t dst = base + isB * 8192 + row * 128 + ((c ^ (row & 7)) << 4);
        asm volatile("cp.async.cg.shared.global [%0], [%1], 16;" :: "r"(dst), "l"(src) : "memory");
    }
    asm volatile("cp.async.commit_group;" ::: "memory");
}

__global__ void __launch_bounds__(256, 1)
gemm2_hmma(const __half* __restrict__ Ah, const __half* __restrict__ Al,
           const __half* __restrict__ Bh, const __half* __restrict__ Bl,
           const float* __restrict__ bias1, const float* __restrict__ bias2,
           float* __restrict__ outf) {
    extern __shared__ char smem[];
    uint32_t sb = smem_u32(smem);
    int tid = threadIdx.x, lane = tid & 31, w = tid >> 5;
    int wm = w & 1, wn = w >> 1;
    int m0 = blockIdx.y * 64, n0 = blockIdx.x * 64;
    const int K = HO, KTP = HO / 64, T = 3 * KTP;

    int lr = lane & 7;
    int rsel = (lane >> 3) & 1;
    int csel = lane >> 4;

    load_tile(sb, 0, 0, KTP, Ah, Al, Bh, Bl, m0, n0, K);
    load_tile(sb, 1, 1, KTP, Ah, Al, Bh, Bl, m0, n0, K);

    float acc[2][2][4] = {};

    for (int t = 0; t < T; ++t) {
        asm volatile("cp.async.wait_group 1;" ::: "memory");
        __syncthreads();
        if (t + 2 < T)
            load_tile(sb, (t + 2) % 3, t + 2, KTP, Ah, Al, Bh, Bl, m0, n0, K);
        else
            asm volatile("cp.async.commit_group;" ::: "memory");

        uint32_t stA = sb + (t % 3) * STG_BYTES;
        uint32_t stB = stA + 8192;
#pragma unroll
        for (int s = 0; s < 4; ++s) {
            uint32_t swz = (uint32_t)(((2 * s + csel) ^ lr) << 4);
            uint32_t aF[2][4], bF[4];
#pragma unroll
            for (int mi = 0; mi < 2; ++mi) {
                uint32_t row = (uint32_t)(wm * 32 + mi * 16 + lr + rsel * 8) * 128;
                ldsm_x4(aF[mi], stA + row + swz);
            }
            {
                uint32_t row = (uint32_t)(wn * 16 + lr + rsel * 8) * 128;
                ldsm_x4(bF, stB + row + swz);
            }
#pragma unroll
            for (int mi = 0; mi < 2; ++mi) {
                mma16816(acc[mi][0], aF[mi], bF[0], bF[2]);
                mma16816(acc[mi][1], aF[mi], bF[1], bF[3]);
            }
        }
        __syncthreads();
    }

    int r = lane >> 2, c2 = (lane & 3) * 2;
#pragma unroll
    for (int mi = 0; mi < 2; ++mi) {
#pragma unroll
        for (int ni = 0; ni < 2; ++ni) {
            int mA = m0 + wm * 32 + mi * 16 + r;
            int n = n0 + wn * 16 + ni * 8 + c2;
            float* a = acc[mi][ni];
            float bb0 = bias1[n] + bias2[n];
            float bb1 = bias1[n + 1] + bias2[n + 1];
            *(float2*)(outf + (size_t)mA * HO + n) =
                make_float2(fmaxf(a[0] + bb0, 0.0f), fmaxf(a[1] + bb1, 0.0f));
            *(float2*)(outf + (size_t)(mA + 8) * HO + n) =
                make_float2(fmaxf(a[2] + bb0, 0.0f), fmaxf(a[3] + bb1, 0.0f));
        }
    }
}

// ---------------------------------------------------------------------------
extern "C" void kernel_launch(void* const* d_in, const int* in_sizes, int n_in,
                              void* d_out, int out_size) {
    const float* x  = (const float*)d_in[0];
    const float* l  = (const float*)d_in[1];
    const float* W1 = (const float*)d_in[2];
    const float* b1 = (const float*)d_in[3];
    const float* W2 = (const float*)d_in[4];
    const float* b2 = (const float*)d_in[5];
    const float* W3 = (const float*)d_in[6];
    const float* b3 = (const float*)d_in[7];
    const float* W4 = (const float*)d_in[8];
    const float* b4 = (const float*)d_in[9];
    float* out = (float*)d_out;

    void *pAhi, *pAlo, *pW1hi, *pW1lo, *pPart, *pActhi, *pActlo, *pW34hi, *pW34lo;
    cudaGetSymbolAddress(&pAhi, g_Ahi);
    cudaGetSymbolAddress(&pAlo, g_Alo);
    cudaGetSymbolAddress(&pW1hi, g_W1hi);
    cudaGetSymbolAddress(&pW1lo, g_W1lo);
    cudaGetSymbolAddress(&pPart, g_part);
    cudaGetSymbolAddress(&pActhi, g_acthi);
    cudaGetSymbolAddress(&pActlo, g_actlo);
    cudaGetSymbolAddress(&pW34hi, g_W34hi);
    cudaGetSymbolAddress(&pW34lo, g_W34lo);

    cudaFuncSetAttribute(gemm1_128, cudaFuncAttributeMaxDynamicSharedMemorySize, SMEM1);
    cudaFuncSetAttribute(gemm2_hmma, cudaFuncAttributeMaxDynamicSharedMemorySize, GEMM_SMEM);

    foveate_kernel<<<B_, 256>>>(x, l, (__half*)pAhi, (__half*)pAlo);

    int n4 = HG_ * DIN / 4;
    conv_split4<<<(n4 + 255) / 256, 256>>>(W1, (__half*)pW1hi, (__half*)pW1lo, n4);
    conv_w34<<<(HO * HO + 255) / 256, 256>>>(W3, W4, (__half*)pW34hi, (__half*)pW34lo);
    where_kernel<<<(B_ * HL_ + 255) / 256, 256>>>(l, W2, b2, (__half*)pActhi, (__half*)pActlo);

    // GEMM1: (512 x 9216) @ (1024 x 9216)^T, 128x128 tiles, split-K=4
    gemm1_128<<<dim3(HG_ / 128, B_ / 128, SPLITK), 256, SMEM1>>>(
        (const __half*)pAhi, (const __half*)pAlo,
        (const __half*)pW1hi, (const __half*)pW1lo, (float*)pPart);

    reduce1_kernel<<<(B_ * HG_ + 255) / 256, 256>>>((const float*)pPart, b1,
                                                    (__half*)pActhi, (__half*)pActlo);

    // GEMM2: (512 x 1152) @ (1152 x 1152)^T -> out (bias3+bias4+relu fused)
    gemm2_hmma<<<dim3(HO / 64, B_ / 64), 256, GEMM_SMEM>>>(
        (const __half*)pActhi, (const __half*)pActlo,
        (const __half*)pW34hi, (const __half*)pW34lo,
        b3, b4, out);
}

// round 13
// speedup vs baseline: 2.6253x; 1.0604x over previous
#include <cuda_runtime.h>
#include <cuda_fp16.h>
#include <cstdint>
#include <math.h>

#define B_    512
#define C_    3
#define DIN   9216
#define HG_   1024
#define HL_   128
#define HO    1152
#define SPLITK 4

// ---------------- scratch (device globals; no allocation allowed) -----------
__device__ __align__(256) __half g_Ahi[(size_t)B_ * DIN];
__device__ __align__(256) __half g_Alo[(size_t)B_ * DIN];
__device__ __align__(256) __half g_W1hi[(size_t)HG_ * DIN];
__device__ __align__(256) __half g_W1lo[(size_t)HG_ * DIN];
__device__ __align__(256) float  g_part[(size_t)SPLITK * B_ * HG_];
__device__ __align__(256) __half g_acthi[(size_t)B_ * HO];
__device__ __align__(256) __half g_actlo[(size_t)B_ * HO];
__device__ __align__(256) __half g_W34hi[(size_t)HO * HO];
__device__ __align__(256) __half g_W34lo[(size_t)HO * HO];

// ---------------- helpers ----------------------------------------------------
__device__ __forceinline__ uint32_t smem_u32(const void* p) {
    uint32_t a;
    asm("{ .reg .u64 t; cvta.to.shared.u64 t, %1; cvt.u32.u64 %0, t; }" : "=r"(a) : "l"(p));
    return a;
}
__device__ __forceinline__ void split_h(float v, __half& h, __half& l) {
    h = __float2half_rn(v);
    l = __float2half_rn(v - __half2float(h));
}
__device__ __forceinline__ void ldsm_x4(uint32_t (&f)[4], uint32_t addr) {
    asm volatile("ldmatrix.sync.aligned.m8n8.x4.shared.b16 {%0,%1,%2,%3}, [%4];"
                 : "=r"(f[0]), "=r"(f[1]), "=r"(f[2]), "=r"(f[3]) : "r"(addr));
}
__device__ __forceinline__ void mma16816(float (&c)[4], const uint32_t (&a)[4],
                                         uint32_t b0, uint32_t b1) {
    asm volatile("mma.sync.aligned.m16n8k16.row.col.f32.f16.f16.f32 "
                 "{%0,%1,%2,%3}, {%4,%5,%6,%7}, {%8,%9}, {%0,%1,%2,%3};"
                 : "+f"(c[0]), "+f"(c[1]), "+f"(c[2]), "+f"(c[3])
                 : "r"(a[0]), "r"(a[1]), "r"(a[2]), "r"(a[3]), "r"(b0), "r"(b1));
}

// ---------------- foveation: emits fp16 hi/lo glimpse rows -------------------
__global__ void foveate_kernel(const float* __restrict__ x,
                               const float* __restrict__ l,
                               __half* __restrict__ ghi, __half* __restrict__ glo) {
    int b = blockIdx.x;
    float l0 = l[2 * b + 0];
    float l1 = l[2 * b + 1];
    int x0 = (int)floorf(0.5f * ((l0 + 1.0f) * 256.0f));
    int y0 = (int)floorf(0.5f * ((l1 + 1.0f) * 256.0f));
    x0 = min(max(x0, 0), 256);
    y0 = min(max(y0, 0), 256);

    const float* xb = x + (size_t)b * C_ * 256 * 256;
    __half* gh = ghi + (size_t)b * DIN;
    __half* gl = glo + (size_t)b * DIN;
    int tid = threadIdx.x;

    for (int idx = tid; idx < 3072; idx += blockDim.x) {
        int c = idx >> 10, q = idx & 1023, i = q >> 5, j = q & 31;
        int r = y0 + i - 16, cc = x0 + j - 16;
        float v = 0.0f;
        if ((unsigned)r < 256u && (unsigned)cc < 256u)
            v = xb[c * 65536 + r * 256 + cc];
        split_h(v, gh[idx], gl[idx]);
    }
    for (int idx = tid; idx < 3072; idx += blockDim.x) {
        int c = idx >> 10, q = idx & 1023, i = q >> 5, j = q & 31;
        int r0 = y0 + 2 * i - 32, c0 = x0 + 2 * j - 32;
        float s = 0.0f;
#pragma unroll
        for (int dr = 0; dr < 2; ++dr) {
            int r = r0 + dr;
            if ((unsigned)r < 256u)
#pragma unroll
                for (int dc = 0; dc < 2; ++dc) {
                    int cc = c0 + dc;
                    if ((unsigned)cc < 256u) s += xb[c * 65536 + r * 256 + cc];
                }
        }
        split_h(s * 0.25f, gh[3072 + idx], gl[3072 + idx]);
    }
    for (int idx = tid; idx < 3072; idx += blockDim.x) {
        int c = idx >> 10, q = idx & 1023, i = q >> 5, j = q & 31;
        int r0 = y0 + 4 * i - 64, c0 = x0 + 4 * j - 64;
        float s = 0.0f;
#pragma unroll
        for (int dr = 0; dr < 4; ++dr) {
            int r = r0 + dr;
            if ((unsigned)r < 256u)
#pragma unroll
                for (int dc = 0; dc < 4; ++dc) {
                    int cc = c0 + dc;
                    if ((unsigned)cc < 256u) s += xb[c * 65536 + r * 256 + cc];
                }
        }
        split_h(s * 0.0625f, gh[6144 + idx], gl[6144 + idx]);
    }
}

// ---------------- fp32 -> fp16 hi/lo converters ------------------------------
__global__ void conv_split4(const float* __restrict__ W,
                            __half* __restrict__ hi, __half* __restrict__ lo, int n4) {
    int i = blockIdx.x * blockDim.x + threadIdx.x;
    if (i >= n4) return;
    float4 v = ((const float4*)W)[i];
    union U { __half h[4]; uint2 u; } uh, ul;
    split_h(v.x, uh.h[0], ul.h[0]);
    split_h(v.y, uh.h[1], ul.h[1]);
    split_h(v.z, uh.h[2], ul.h[2]);
    split_h(v.w, uh.h[3], ul.h[3]);
    ((uint2*)hi)[i] = uh.u;
    ((uint2*)lo)[i] = ul.u;
}

__global__ void conv_w34(const float* __restrict__ W3, const float* __restrict__ W4,
                         __half* __restrict__ hi, __half* __restrict__ lo) {
    int idx = blockIdx.x * blockDim.x + threadIdx.x;
    if (idx >= HO * HO) return;
    int n = idx / HO, k = idx - n * HO;
    float w = (k < HG_) ? W3[(size_t)n * HG_ + k] : W4[(size_t)n * HL_ + (k - HG_)];
    split_h(w, hi[idx], lo[idx]);
}

// ---------------- hw = relu(l@W2^T + b2) -> act cols [1024,1152) -------------
__global__ void where_kernel(const float* __restrict__ l,
                             const float* __restrict__ W2,
                             const float* __restrict__ b2,
                             __half* __restrict__ acthi, __half* __restrict__ actlo) {
    int idx = blockIdx.x * blockDim.x + threadIdx.x;
    if (idx >= B_ * HL_) return;
    int b = idx >> 7, o = idx & 127;
    float v = b2[o] + l[2 * b] * W2[2 * o] + l[2 * b + 1] * W2[2 * o + 1];
    v = fmaxf(v, 0.0f);
    split_h(v, acthi[(size_t)b * HO + HG_ + o], actlo[(size_t)b * HO + HG_ + o]);
}

// ---------------- split-K reduce + bias + relu + re-split --------------------
__global__ void reduce1_kernel(const float* __restrict__ part,
                               const float* __restrict__ b1,
                               __half* __restrict__ acthi, __half* __restrict__ actlo) {
    int idx = blockIdx.x * blockDim.x + threadIdx.x;
    if (idx >= B_ * HG_) return;
    const int S = B_ * HG_;
    float s = part[idx] + part[idx + S] + part[idx + 2 * S] + part[idx + 3 * S];
    int m = idx >> 10, n = idx & 1023;
    s = fmaxf(s + b1[n], 0.0f);
    __half h, lo;
    split_h(s, h, lo);
    acthi[(size_t)m * HO + n] = h;
    actlo[(size_t)m * HO + n] = lo;
}

// ============================================================================
// GEMM1: 128x128 CTA tile, BK=64, split-K=4, 8 warps (warp tile 64x32).
// All 4 operand buffers (Ahi,Alo,Bhi,Blo) resident per stage; 3 MMA passes
// (hi*hi + hi*lo + lo*hi) per k-tile. 3-stage cp.async pipeline (192KB smem).
// ============================================================================
#define STG1   65536              // 4 buffers * 128 rows * 128B
#define SMEM1  (3 * STG1)
#define ABUF_HI 0
#define ABUF_LO 16384
#define BBUF_HI 32768
#define BBUF_LO 49152

__device__ __forceinline__ void load_tile_all(uint32_t sb, int stage, int kt,
                                              const __half* __restrict__ Ah,
                                              const __half* __restrict__ Al,
                                              const __half* __restrict__ Bh,
                                              const __half* __restrict__ Bl,
                                              int m0, int n0, int kbase) {
    int k0 = kbase + kt * 64;
    uint32_t base = sb + stage * STG1;
    int tid = threadIdx.x;
#pragma unroll
    for (int i = 0; i < 16; ++i) {
        int cid = i * 256 + tid;            // 0..4095 chunks of 16B
        int buf = cid >> 10;                // 0:Ahi 1:Alo 2:Bhi 3:Blo
        int rem = cid & 1023;
        int row = rem >> 3, c = rem & 7;
        const __half* src;
        if (buf == 0)      src = Ah + (size_t)(m0 + row) * DIN + k0 + c * 8;
        else if (buf == 1) src = Al + (size_t)(m0 + row) * DIN + k0 + c * 8;
        else if (buf == 2) src = Bh + (size_t)(n0 + row) * DIN + k0 + c * 8;
        else               src = Bl + (size_t)(n0 + row) * DIN + k0 + c * 8;
        uint32_t dst = base + buf * 16384 + row * 128 + ((c ^ (row & 7)) << 4);
        asm volatile("cp.async.cg.shared.global [%0], [%1], 16;" :: "r"(dst), "l"(src) : "memory");
    }
    asm volatile("cp.async.commit_group;" ::: "memory");
}

__global__ void __launch_bounds__(256, 1)
gemm1_128(const __half* __restrict__ Ah, const __half* __restrict__ Al,
          const __half* __restrict__ Bh, const __half* __restrict__ Bl,
          float* __restrict__ part) {
    extern __shared__ char smem[];
    uint32_t sb = smem_u32(smem);
    int tid = threadIdx.x, lane = tid & 31, w = tid >> 5;
    int wm = w & 1, wn = w >> 1;            // 2 x 4 warps; warp tile 64 x 32
    int m0 = blockIdx.y * 128, n0 = blockIdx.x * 128;
    const int T = DIN / (SPLITK * 64);      // 36 k-tiles
    int kbase = blockIdx.z * (DIN / SPLITK);
    part += (size_t)blockIdx.z * B_ * HG_;

    int lr = lane & 7;
    int rsel = (lane >> 3) & 1;
    int csel = lane >> 4;

    uint32_t offA[4], offB[2];
#pragma unroll
    for (int mi = 0; mi < 4; ++mi)
        offA[mi] = (uint32_t)(wm * 64 + mi * 16 + lr + rsel * 8) * 128;
#pragma unroll
    for (int bi = 0; bi < 2; ++bi)
        offB[bi] = (uint32_t)(wn * 32 + bi * 16 + lr + rsel * 8) * 128;

    load_tile_all(sb, 0, 0, Ah, Al, Bh, Bl, m0, n0, kbase);
    load_tile_all(sb, 1, 1, Ah, Al, Bh, Bl, m0, n0, kbase);

    float acc[4][4][4] = {};

    for (int t = 0; t < T; ++t) {
        asm volatile("cp.async.wait_group 1;" ::: "memory");
        __syncthreads();
        if (t + 2 < T)
            load_tile_all(sb, (t + 2) % 3, t + 2, Ah, Al, Bh, Bl, m0, n0, kbase);
        else
            asm volatile("cp.async.commit_group;" ::: "memory");

        uint32_t st = sb + (t % 3) * STG1;
#pragma unroll
        for (int s = 0; s < 4; ++s) {
            uint32_t swz = (uint32_t)(((2 * s + csel) ^ lr) << 4);
            uint32_t aHi[4][4], aLo[4][4], bHi[2][4], bLo[2][4];
#pragma unroll
            for (int mi = 0; mi < 4; ++mi) {
                ldsm_x4(aHi[mi], st + ABUF_HI + offA[mi] + swz);
                ldsm_x4(aLo[mi], st + ABUF_LO + offA[mi] + swz);
            }
#pragma unroll
            for (int bi = 0; bi < 2; ++bi) {
                ldsm_x4(bHi[bi], st + BBUF_HI + offB[bi] + swz);
                ldsm_x4(bLo[bi], st + BBUF_LO + offB[bi] + swz);
            }
#pragma unroll
            for (int mi = 0; mi < 4; ++mi)
#pragma unroll
                for (int j = 0; j < 4; ++j) {
                    uint32_t b0h = bHi[j >> 1][j & 1], b1h = bHi[j >> 1][(j & 1) + 2];
                    uint32_t b0l = bLo[j >> 1][j & 1], b1l = bLo[j >> 1][(j & 1) + 2];
                    mma16816(acc[mi][j], aHi[mi], b0h, b1h);   // hi*hi
                    mma16816(acc[mi][j], aHi[mi], b0l, b1l);   // hi*lo
                    mma16816(acc[mi][j], aLo[mi], b0h, b1h);   // lo*hi
                }
        }
        __syncthreads();
    }

    // partial store (fp32, no bias)
    int r = lane >> 2, c2 = (lane & 3) * 2;
#pragma unroll
    for (int mi = 0; mi < 4; ++mi) {
#pragma unroll
        for (int j = 0; j < 4; ++j) {
            int mA = m0 + wm * 64 + mi * 16 + r;
            int n = n0 + wn * 32 + j * 8 + c2;
            float* a = acc[mi][j];
            *(float2*)(part + (size_t)mA * HG_ + n) = make_float2(a[0], a[1]);
            *(float2*)(part + (size_t)(mA + 8) * HG_ + n) = make_float2(a[2], a[3]);
        }
    }
}

// ============================================================================
// GEMM2: 64x64 tile HMMA kernel (proven R8 path), bias3+bias4+relu epilogue.
// ============================================================================
#define STG_BYTES 16384
#define GEMM_SMEM (3 * STG_BYTES)

__device__ __forceinline__ void load_tile(uint32_t sb, int stage, int t, int KTP,
                                          const __half* __restrict__ Ah,
                                          const __half* __restrict__ Al,
                                          const __half* __restrict__ Bh,
                                          const __half* __restrict__ Bl,
                                          int m0, int n0, int K) {
    int p = 0, kk = t;
    if (kk >= KTP) { p = 1; kk -= KTP; }
    if (kk >= KTP) { p = 2; kk -= KTP; }
    const __half* As = (p == 1) ? Al : Ah;
    const __half* Bs = (p == 2) ? Bl : Bh;
    int k0 = kk * 64;
    uint32_t base = sb + stage * STG_BYTES;
    int tid = threadIdx.x;
#pragma unroll
    for (int i = 0; i < 4; ++i) {
        int cid = i * 256 + tid;
        int isB = cid >> 9;
        int rem = cid & 511;
        int row = rem >> 3, c = rem & 7;
        const __half* src = isB ? (Bs + (size_t)(n0 + row) * K + k0 + c * 8)
                                : (As + (size_t)(m0 + row) * K + k0 + c * 8);
        uint32_t dst = base + isB * 8192 + row * 128 + ((c ^ (row & 7)) << 4);
        asm volatile("cp.async.cg.shared.global [%0], [%1], 16;" :: "r"(dst), "l"(src) : "memory");
    }
    asm volatile("cp.async.commit_group;" ::: "memory");
}

__global__ void __launch_bounds__(256, 1)
gemm2_hmma(const __half* __restrict__ Ah, const __half* __restrict__ Al,
           const __half* __restrict__ Bh, const __half* __restrict__ Bl,
           const float* __restrict__ bias1, const float* __restrict__ bias2,
           float* __restrict__ outf) {
    extern __shared__ char smem[];
    uint32_t sb = smem_u32(smem);
    int tid = threadIdx.x, lane = tid & 31, w = tid >> 5;
    int wm = w & 1, wn = w >> 1;
    int m0 = blockIdx.y * 64, n0 = blockIdx.x * 64;
    const int K = HO, KTP = HO / 64, T = 3 * KTP;

    int lr = lane & 7;
    int rsel = (lane >> 3) & 1;
    int csel = lane >> 4;

    load_tile(sb, 0, 0, KTP, Ah, Al, Bh, Bl, m0, n0, K);
    load_tile(sb, 1, 1, KTP, Ah, Al, Bh, Bl, m0, n0, K);

    float acc[2][2][4] = {};

    for (int t = 0; t < T; ++t) {
        asm volatile("cp.async.wait_group 1;" ::: "memory");
        __syncthreads();
        if (t + 2 < T)
            load_tile(sb, (t + 2) % 3, t + 2, KTP, Ah, Al, Bh, Bl, m0, n0, K);
        else
            asm volatile("cp.async.commit_group;" ::: "memory");

        uint32_t stA = sb + (t % 3) * STG_BYTES;
        uint32_t stB = stA + 8192;
#pragma unroll
        for (int s = 0; s < 4; ++s) {
            uint32_t swz = (uint32_t)(((2 * s + csel) ^ lr) << 4);
            uint32_t aF[2][4], bF[4];
#pragma unroll
            for (int mi = 0; mi < 2; ++mi) {
                uint32_t row = (uint32_t)(wm * 32 + mi * 16 + lr + rsel * 8) * 128;
                ldsm_x4(aF[mi], stA + row + swz);
            }
            {
                uint32_t row = (uint32_t)(wn * 16 + lr + rsel * 8) * 128;
                ldsm_x4(bF, stB + row + swz);
            }
#pragma unroll
            for (int mi = 0; mi < 2; ++mi) {
                mma16816(acc[mi][0], aF[mi], bF[0], bF[2]);
                mma16816(acc[mi][1], aF[mi], bF[1], bF[3]);
            }
        }
        __syncthreads();
    }

    int r = lane >> 2, c2 = (lane & 3) * 2;
#pragma unroll
    for (int mi = 0; mi < 2; ++mi) {
#pragma unroll
        for (int ni = 0; ni < 2; ++ni) {
            int mA = m0 + wm * 32 + mi * 16 + r;
            int n = n0 + wn * 16 + ni * 8 + c2;
            float* a = acc[mi][ni];
            float bb0 = bias1[n] + bias2[n];
            float bb1 = bias1[n + 1] + bias2[n + 1];
            *(float2*)(outf + (size_t)mA * HO + n) =
                make_float2(fmaxf(a[0] + bb0, 0.0f), fmaxf(a[1] + bb1, 0.0f));
            *(float2*)(outf + (size_t)(mA + 8) * HO + n) =
                make_float2(fmaxf(a[2] + bb0, 0.0f), fmaxf(a[3] + bb1, 0.0f));
        }
    }
}

// ---------------------------------------------------------------------------
extern "C" void kernel_launch(void* const* d_in, const int* in_sizes, int n_in,
                              void* d_out, int out_size) {
    const float* x  = (const float*)d_in[0];
    const float* l  = (const float*)d_in[1];
    const float* W1 = (const float*)d_in[2];
    const float* b1 = (const float*)d_in[3];
    const float* W2 = (const float*)d_in[4];
    const float* b2 = (const float*)d_in[5];
    const float* W3 = (const float*)d_in[6];
    const float* b3 = (const float*)d_in[7];
    const float* W4 = (const float*)d_in[8];
    const float* b4 = (const float*)d_in[9];
    float* out = (float*)d_out;

    void *pAhi, *pAlo, *pW1hi, *pW1lo, *pPart, *pActhi, *pActlo, *pW34hi, *pW34lo;
    cudaGetSymbolAddress(&pAhi, g_Ahi);
    cudaGetSymbolAddress(&pAlo, g_Alo);
    cudaGetSymbolAddress(&pW1hi, g_W1hi);
    cudaGetSymbolAddress(&pW1lo, g_W1lo);
    cudaGetSymbolAddress(&pPart, g_part);
    cudaGetSymbolAddress(&pActhi, g_acthi);
    cudaGetSymbolAddress(&pActlo, g_actlo);
    cudaGetSymbolAddress(&pW34hi, g_W34hi);
    cudaGetSymbolAddress(&pW34lo, g_W34lo);

    cudaFuncSetAttribute(gemm1_128, cudaFuncAttributeMaxDynamicSharedMemorySize, SMEM1);
    cudaFuncSetAttribute(gemm2_hmma, cudaFuncAttributeMaxDynamicSharedMemorySize, GEMM_SMEM);

    foveate_kernel<<<B_, 256>>>(x, l, (__half*)pAhi, (__half*)pAlo);

    int n4 = HG_ * DIN / 4;
    conv_split4<<<(n4 + 255) / 256, 256>>>(W1, (__half*)pW1hi, (__half*)pW1lo, n4);
    conv_w34<<<(HO * HO + 255) / 256, 256>>>(W3, W4, (__half*)pW34hi, (__half*)pW34lo);
    where_kernel<<<(B_ * HL_ + 255) / 256, 256>>>(l, W2, b2, (__half*)pActhi, (__half*)pActlo);

    // GEMM1: (512 x 9216) @ (1024 x 9216)^T, 128x128 tiles, split-K=4,
    // all-buffers-resident 3-pass MMA per k-tile
    gemm1_128<<<dim3(HG_ / 128, B_ / 128, SPLITK), 256, SMEM1>>>(
        (const __half*)pAhi, (const __half*)pAlo,
        (const __half*)pW1hi, (const __half*)pW1lo, (float*)pPart);

    reduce1_kernel<<<(B_ * HG_ + 255) / 256, 256>>>((const float*)pPart, b1,
                                                    (__half*)pActhi, (__half*)pActlo);

    // GEMM2: (512 x 1152) @ (1152 x 1152)^T -> out (bias3+bias4+relu fused)
    gemm2_hmma<<<dim3(HO / 64, B_ / 64), 256, GEMM_SMEM>>>(
        (const __half*)pActhi, (const __half*)pActlo,
        (const __half*)pW34hi, (const __half*)pW34lo,
        b3, b4, out);
}

// round 14
// speedup vs baseline: 3.3023x; 1.2578x over previous
#include <cuda_runtime.h>
#include <cuda_fp16.h>
#include <cstdint>
#include <math.h>

#define B_    512
#define C_    3
#define DIN   9216
#define HG_   1024
#define HL_   128
#define HO    1152
#define SPLITK 4

// ---------------- scratch (device globals; no allocation allowed) -----------
__device__ __align__(256) __half g_Ahi[(size_t)B_ * DIN];
__device__ __align__(256) __half g_Alo[(size_t)B_ * DIN];
__device__ __align__(256) __half g_W1hi[(size_t)HG_ * DIN];
__device__ __align__(256) float  g_part[(size_t)SPLITK * B_ * HG_];
__device__ __align__(256) __half g_acthi[(size_t)B_ * HO];
__device__ __align__(256) __half g_actlo[(size_t)B_ * HO];
__device__ __align__(256) __half g_W34hi[(size_t)HO * HO];

// ---------------- helpers ----------------------------------------------------
__device__ __forceinline__ uint32_t smem_u32(const void* p) {
    uint32_t a;
    asm("{ .reg .u64 t; cvta.to.shared.u64 t, %1; cvt.u32.u64 %0, t; }" : "=r"(a) : "l"(p));
    return a;
}
__device__ __forceinline__ void split_h(float v, __half& h, __half& l) {
    h = __float2half_rn(v);
    l = __float2half_rn(v - __half2float(h));
}
__device__ __forceinline__ void ldsm_x4(uint32_t (&f)[4], uint32_t addr) {
    asm volatile("ldmatrix.sync.aligned.m8n8.x4.shared.b16 {%0,%1,%2,%3}, [%4];"
                 : "=r"(f[0]), "=r"(f[1]), "=r"(f[2]), "=r"(f[3]) : "r"(addr));
}
__device__ __forceinline__ void mma16816(float (&c)[4], const uint32_t (&a)[4],
                                         uint32_t b0, uint32_t b1) {
    asm volatile("mma.sync.aligned.m16n8k16.row.col.f32.f16.f16.f32 "
                 "{%0,%1,%2,%3}, {%4,%5,%6,%7}, {%8,%9}, {%0,%1,%2,%3};"
                 : "+f"(c[0]), "+f"(c[1]), "+f"(c[2]), "+f"(c[3])
                 : "r"(a[0]), "r"(a[1]), "r"(a[2]), "r"(a[3]), "r"(b0), "r"(b1));
}

// ---------------- foveation: emits fp16 hi/lo glimpse rows -------------------
__global__ void foveate_kernel(const float* __restrict__ x,
                               const float* __restrict__ l,
                               __half* __restrict__ ghi, __half* __restrict__ glo) {
    int b = blockIdx.x;
    float l0 = l[2 * b + 0];
    float l1 = l[2 * b + 1];
    int x0 = (int)floorf(0.5f * ((l0 + 1.0f) * 256.0f));
    int y0 = (int)floorf(0.5f * ((l1 + 1.0f) * 256.0f));
    x0 = min(max(x0, 0), 256);
    y0 = min(max(y0, 0), 256);

    const float* xb = x + (size_t)b * C_ * 256 * 256;
    __half* gh = ghi + (size_t)b * DIN;
    __half* gl = glo + (size_t)b * DIN;
    int tid = threadIdx.x;

    for (int idx = tid; idx < 3072; idx += blockDim.x) {
        int c = idx >> 10, q = idx & 1023, i = q >> 5, j = q & 31;
        int r = y0 + i - 16, cc = x0 + j - 16;
        float v = 0.0f;
        if ((unsigned)r < 256u && (unsigned)cc < 256u)
            v = xb[c * 65536 + r * 256 + cc];
        split_h(v, gh[idx], gl[idx]);
    }
    for (int idx = tid; idx < 3072; idx += blockDim.x) {
        int c = idx >> 10, q = idx & 1023, i = q >> 5, j = q & 31;
        int r0 = y0 + 2 * i - 32, c0 = x0 + 2 * j - 32;
        float s = 0.0f;
#pragma unroll
        for (int dr = 0; dr < 2; ++dr) {
            int r = r0 + dr;
            if ((unsigned)r < 256u)
#pragma unroll
                for (int dc = 0; dc < 2; ++dc) {
                    int cc = c0 + dc;
                    if ((unsigned)cc < 256u) s += xb[c * 65536 + r * 256 + cc];
                }
        }
        split_h(s * 0.25f, gh[3072 + idx], gl[3072 + idx]);
    }
    for (int idx = tid; idx < 3072; idx += blockDim.x) {
        int c = idx >> 10, q = idx & 1023, i = q >> 5, j = q & 31;
        int r0 = y0 + 4 * i - 64, c0 = x0 + 4 * j - 64;
        float s = 0.0f;
#pragma unroll
        for (int dr = 0; dr < 4; ++dr) {
            int r = r0 + dr;
            if ((unsigned)r < 256u)
#pragma unroll
                for (int dc = 0; dc < 4; ++dc) {
                    int cc = c0 + dc;
                    if ((unsigned)cc < 256u) s += xb[c * 65536 + r * 256 + cc];
                }
        }
        split_h(s * 0.0625f, gh[6144 + idx], gl[6144 + idx]);
    }
}

// ---------------- fp32 -> fp16 (hi only) converters --------------------------
__global__ void conv_hi4(const float* __restrict__ W, __half* __restrict__ hi, int n4) {
    int i = blockIdx.x * blockDim.x + threadIdx.x;
    if (i >= n4) return;
    float4 v = ((const float4*)W)[i];
    union U { __half h[4]; uint2 u; } uh;
    uh.h[0] = __float2half_rn(v.x);
    uh.h[1] = __float2half_rn(v.y);
    uh.h[2] = __float2half_rn(v.z);
    uh.h[3] = __float2half_rn(v.w);
    ((uint2*)hi)[i] = uh.u;
}

__global__ void conv_w34hi(const float* __restrict__ W3, const float* __restrict__ W4,
                           __half* __restrict__ hi) {
    int idx = blockIdx.x * blockDim.x + threadIdx.x;
    if (idx >= HO * HO) return;
    int n = idx / HO, k = idx - n * HO;
    float w = (k < HG_) ? W3[(size_t)n * HG_ + k] : W4[(size_t)n * HL_ + (k - HG_)];
    hi[idx] = __float2half_rn(w);
}

// ---------------- hw = relu(l@W2^T + b2) -> act cols [1024,1152) -------------
__global__ void where_kernel(const float* __restrict__ l,
                             const float* __restrict__ W2,
                             const float* __restrict__ b2,
                             __half* __restrict__ acthi, __half* __restrict__ actlo) {
    int idx = blockIdx.x * blockDim.x + threadIdx.x;
    if (idx >= B_ * HL_) return;
    int b = idx >> 7, o = idx & 127;
    float v = b2[o] + l[2 * b] * W2[2 * o] + l[2 * b + 1] * W2[2 * o + 1];
    v = fmaxf(v, 0.0f);
    split_h(v, acthi[(size_t)b * HO + HG_ + o], actlo[(size_t)b * HO + HG_ + o]);
}

// ---------------- split-K reduce + bias + relu + re-split --------------------
__global__ void reduce1_kernel(const float* __restrict__ part,
                               const float* __restrict__ b1,
                               __half* __restrict__ acthi, __half* __restrict__ actlo) {
    int idx = blockIdx.x * blockDim.x + threadIdx.x;
    if (idx >= B_ * HG_) return;
    const int S = B_ * HG_;
    float s = part[idx] + part[idx + S] + part[idx + 2 * S] + part[idx + 3 * S];
    int m = idx >> 10, n = idx & 1023;
    s = fmaxf(s + b1[n], 0.0f);
    __half h, lo;
    split_h(s, h, lo);
    acthi[(size_t)m * HO + n] = h;
    actlo[(size_t)m * HO + n] = lo;
}

// ============================================================================
// GEMM1: 128x128 CTA tile, BK=64, split-K=4, 8 warps (warp tile 64x32).
// 2-pass: (Ahi + Alo) @ W1hi. Buffers Ahi, Alo, Bhi resident per stage.
// 3-stage cp.async pipeline (144KB smem).
// ============================================================================
#define STG1   49152              // 3 buffers * 128 rows * 128B
#define SMEM1  (3 * STG1)
#define ABUF_HI 0
#define ABUF_LO 16384
#define BBUF_HI 32768

__device__ __forceinline__ void load_tile_all(uint32_t sb, int stage, int kt,
                                              const __half* __restrict__ Ah,
                                              const __half* __restrict__ Al,
                                              const __half* __restrict__ Bh,
                                              int m0, int n0, int kbase) {
    int k0 = kbase + kt * 64;
    uint32_t base = sb + stage * STG1;
    int tid = threadIdx.x;
#pragma unroll
    for (int i = 0; i < 12; ++i) {
        int cid = i * 256 + tid;            // 0..3071 chunks of 16B
        int buf = cid >> 10;                // 0:Ahi 1:Alo 2:Bhi
        int rem = cid & 1023;
        int row = rem >> 3, c = rem & 7;
        const __half* src;
        if (buf == 0)      src = Ah + (size_t)(m0 + row) * DIN + k0 + c * 8;
        else if (buf == 1) src = Al + (size_t)(m0 + row) * DIN + k0 + c * 8;
        else               src = Bh + (size_t)(n0 + row) * DIN + k0 + c * 8;
        uint32_t dst = base + buf * 16384 + row * 128 + ((c ^ (row & 7)) << 4);
        asm volatile("cp.async.cg.shared.global [%0], [%1], 16;" :: "r"(dst), "l"(src) : "memory");
    }
    asm volatile("cp.async.commit_group;" ::: "memory");
}

__global__ void __launch_bounds__(256, 1)
gemm1_128(const __half* __restrict__ Ah, const __half* __restrict__ Al,
          const __half* __restrict__ Bh, float* __restrict__ part) {
    extern __shared__ char smem[];
    uint32_t sb = smem_u32(smem);
    int tid = threadIdx.x, lane = tid & 31, w = tid >> 5;
    int wm = w & 1, wn = w >> 1;            // 2 x 4 warps; warp tile 64 x 32
    int m0 = blockIdx.y * 128, n0 = blockIdx.x * 128;
    const int T = DIN / (SPLITK * 64);      // 36 k-tiles
    int kbase = blockIdx.z * (DIN / SPLITK);
    part += (size_t)blockIdx.z * B_ * HG_;

    int lr = lane & 7;
    int rsel = (lane >> 3) & 1;
    int csel = lane >> 4;

    uint32_t offA[4], offB[2];
#pragma unroll
    for (int mi = 0; mi < 4; ++mi)
        offA[mi] = (uint32_t)(wm * 64 + mi * 16 + lr + rsel * 8) * 128;
#pragma unroll
    for (int bi = 0; bi < 2; ++bi)
        offB[bi] = (uint32_t)(wn * 32 + bi * 16 + lr + rsel * 8) * 128;

    load_tile_all(sb, 0, 0, Ah, Al, Bh, m0, n0, kbase);
    load_tile_all(sb, 1, 1, Ah, Al, Bh, m0, n0, kbase);

    float acc[4][4][4] = {};

    for (int t = 0; t < T; ++t) {
        asm volatile("cp.async.wait_group 1;" ::: "memory");
        __syncthreads();
        if (t + 2 < T)
            load_tile_all(sb, (t + 2) % 3, t + 2, Ah, Al, Bh, m0, n0, kbase);
        else
            asm volatile("cp.async.commit_group;" ::: "memory");

        uint32_t st = sb + (t % 3) * STG1;
#pragma unroll
        for (int s = 0; s < 4; ++s) {
            uint32_t swz = (uint32_t)(((2 * s + csel) ^ lr) << 4);
            uint32_t aHi[4][4], aLo[4][4], bHi[2][4];
#pragma unroll
            for (int mi = 0; mi < 4; ++mi) {
                ldsm_x4(aHi[mi], st + ABUF_HI + offA[mi] + swz);
                ldsm_x4(aLo[mi], st + ABUF_LO + offA[mi] + swz);
            }
#pragma unroll
            for (int bi = 0; bi < 2; ++bi)
                ldsm_x4(bHi[bi], st + BBUF_HI + offB[bi] + swz);
#pragma unroll
            for (int mi = 0; mi < 4; ++mi)
#pragma unroll
                for (int j = 0; j < 4; ++j) {
                    uint32_t b0 = bHi[j >> 1][j & 1], b1 = bHi[j >> 1][(j & 1) + 2];
                    mma16816(acc[mi][j], aHi[mi], b0, b1);   // hi*hi
                    mma16816(acc[mi][j], aLo[mi], b0, b1);   // lo*hi
                }
        }
        __syncthreads();
    }

    // partial store (fp32, no bias)
    int r = lane >> 2, c2 = (lane & 3) * 2;
#pragma unroll
    for (int mi = 0; mi < 4; ++mi) {
#pragma unroll
        for (int j = 0; j < 4; ++j) {
            int mA = m0 + wm * 64 + mi * 16 + r;
            int n = n0 + wn * 32 + j * 8 + c2;
            float* a = acc[mi][j];
            *(float2*)(part + (size_t)mA * HG_ + n) = make_float2(a[0], a[1]);
            *(float2*)(part + (size_t)(mA + 8) * HG_ + n) = make_float2(a[2], a[3]);
        }
    }
}

// ============================================================================
// GEMM2: 64x64 CTA tile, 2-pass: (acthi + actlo) @ W34hi.
// Buffers acthi, actlo, w34hi resident per stage; 3-stage pipeline (72KB).
// ============================================================================
#define STG2  24576               // 3 buffers * 64 rows * 128B
#define SMEM2 (3 * STG2)

__device__ __forceinline__ void load_tile2(uint32_t sb, int stage, int kt,
                                           const __half* __restrict__ Ah,
                                           const __half* __restrict__ Al,
                                           const __half* __restrict__ Bh,
                                           int m0, int n0) {
    int k0 = kt * 64;
    uint32_t base = sb + stage * STG2;
    int tid = threadIdx.x;
#pragma unroll
    for (int i = 0; i < 6; ++i) {
        int cid = i * 256 + tid;            // 0..1535
        int buf = cid >> 9;                 // 0:acthi 1:actlo 2:w34hi
        int rem = cid & 511;
        int row = rem >> 3, c = rem & 7;
        const __half* src;
        if (buf == 0)      src = Ah + (size_t)(m0 + row) * HO + k0 + c * 8;
        else if (buf == 1) src = Al + (size_t)(m0 + row) * HO + k0 + c * 8;
        else               src = Bh + (size_t)(n0 + row) * HO + k0 + c * 8;
        uint32_t dst = base + buf * 8192 + row * 128 + ((c ^ (row & 7)) << 4);
        asm volatile("cp.async.cg.shared.global [%0], [%1], 16;" :: "r"(dst), "l"(src) : "memory");
    }
    asm volatile("cp.async.commit_group;" ::: "memory");
}

__global__ void __launch_bounds__(256, 1)
gemm2_hmma(const __half* __restrict__ Ah, const __half* __restrict__ Al,
           const __half* __restrict__ Bh,
           const float* __restrict__ bias1, const float* __restrict__ bias2,
           float* __restrict__ outf) {
    extern __shared__ char smem[];
    uint32_t sb = smem_u32(smem);
    int tid = threadIdx.x, lane = tid & 31, w = tid >> 5;
    int wm = w & 1, wn = w >> 1;            // warp tile 32x16
    int m0 = blockIdx.y * 64, n0 = blockIdx.x * 64;
    const int T = HO / 64;                  // 18 k-tiles

    int lr = lane & 7;
    int rsel = (lane >> 3) & 1;
    int csel = lane >> 4;

    uint32_t offA[2], offB;
#pragma unroll
    for (int mi = 0; mi < 2; ++mi)
        offA[mi] = (uint32_t)(wm * 32 + mi * 16 + lr + rsel * 8) * 128;
    offB = (uint32_t)(wn * 16 + lr + rsel * 8) * 128;

    load_tile2(sb, 0, 0, Ah, Al, Bh, m0, n0);
    load_tile2(sb, 1, 1, Ah, Al, Bh, m0, n0);

    float acc[2][2][4] = {};

    for (int t = 0; t < T; ++t) {
        asm volatile("cp.async.wait_group 1;" ::: "memory");
        __syncthreads();
        if (t + 2 < T)
            load_tile2(sb, (t + 2) % 3, t + 2, Ah, Al, Bh, m0, n0);
        else
            asm volatile("cp.async.commit_group;" ::: "memory");

        uint32_t st = sb + (t % 3) * STG2;
#pragma unroll
        for (int s = 0; s < 4; ++s) {
            uint32_t swz = (uint32_t)(((2 * s + csel) ^ lr) << 4);
            uint32_t aHi[2][4], aLo[2][4], bF[4];
#pragma unroll
            for (int mi = 0; mi < 2; ++mi) {
                ldsm_x4(aHi[mi], st + 0    + offA[mi] + swz);
                ldsm_x4(aLo[mi], st + 8192 + offA[mi] + swz);
            }
            ldsm_x4(bF, st + 16384 + offB + swz);
#pragma unroll
            for (int mi = 0; mi < 2; ++mi) {
                mma16816(acc[mi][0], aHi[mi], bF[0], bF[2]);
                mma16816(acc[mi][1], aHi[mi], bF[1], bF[3]);
                mma16816(acc[mi][0], aLo[mi], bF[0], bF[2]);
                mma16816(acc[mi][1], aLo[mi], bF[1], bF[3]);
            }
        }
        __syncthreads();
    }

    int r = lane >> 2, c2 = (lane & 3) * 2;
#pragma unroll
    for (int mi = 0; mi < 2; ++mi) {
#pragma unroll
        for (int ni = 0; ni < 2; ++ni) {
            int mA = m0 + wm * 32 + mi * 16 + r;
            int n = n0 + wn * 16 + ni * 8 + c2;
            float* a = acc[mi][ni];
            float bb0 = bias1[n] + bias2[n];
            float bb1 = bias1[n + 1] + bias2[n + 1];
            *(float2*)(outf + (size_t)mA * HO + n) =
                make_float2(fmaxf(a[0] + bb0, 0.0f), fmaxf(a[1] + bb1, 0.0f));
            *(float2*)(outf + (size_t)(mA + 8) * HO + n) =
                make_float2(fmaxf(a[2] + bb0, 0.0f), fmaxf(a[3] + bb1, 0.0f));
        }
    }
}

// ---------------------------------------------------------------------------
extern "C" void kernel_launch(void* const* d_in, const int* in_sizes, int n_in,
                              void* d_out, int out_size) {
    const float* x  = (const float*)d_in[0];
    const float* l  = (const float*)d_in[1];
    const float* W1 = (const float*)d_in[2];
    const float* b1 = (const float*)d_in[3];
    const float* W2 = (const float*)d_in[4];
    const float* b2 = (const float*)d_in[5];
    const float* W3 = (const float*)d_in[6];
    const float* b3 = (const float*)d_in[7];
    const float* W4 = (const float*)d_in[8];
    const float* b4 = (const float*)d_in[9];
    float* out = (float*)d_out;

    void *pAhi, *pAlo, *pW1hi, *pPart, *pActhi, *pActlo, *pW34hi;
    cudaGetSymbolAddress(&pAhi, g_Ahi);
    cudaGetSymbolAddress(&pAlo, g_Alo);
    cudaGetSymbolAddress(&pW1hi, g_W1hi);
    cudaGetSymbolAddress(&pPart, g_part);
    cudaGetSymbolAddress(&pActhi, g_acthi);
    cudaGetSymbolAddress(&pActlo, g_actlo);
    cudaGetSymbolAddress(&pW34hi, g_W34hi);

    cudaFuncSetAttribute(gemm1_128, cudaFuncAttributeMaxDynamicSharedMemorySize, SMEM1);
    cudaFuncSetAttribute(gemm2_hmma, cudaFuncAttributeMaxDynamicSharedMemorySize, SMEM2);

    foveate_kernel<<<B_, 256>>>(x, l, (__half*)pAhi, (__half*)pAlo);

    int n4 = HG_ * DIN / 4;
    conv_hi4<<<(n4 + 255) / 256, 256>>>(W1, (__half*)pW1hi, n4);
    conv_w34hi<<<(HO * HO + 255) / 256, 256>>>(W3, W4, (__half*)pW34hi);
    where_kernel<<<(B_ * HL_ + 255) / 256, 256>>>(l, W2, b2, (__half*)pActhi, (__half*)pActlo);

    // GEMM1: (512 x 9216) @ (1024 x 9216)^T, 128x128 tiles, split-K=4, 2-pass
    gemm1_128<<<dim3(HG_ / 128, B_ / 128, SPLITK), 256, SMEM1>>>(
        (const __half*)pAhi, (const __half*)pAlo,
        (const __half*)pW1hi, (float*)pPart);

    reduce1_kernel<<<(B_ * HG_ + 255) / 256, 256>>>((const float*)pPart, b1,
                                                    (__half*)pActhi, (__half*)pActlo);

    // GEMM2: (512 x 1152) @ (1152 x 1152)^T -> out, 2-pass, bias+relu fused
    gemm2_hmma<<<dim3(HO / 64, B_ / 64), 256, SMEM2>>>(
        (const __half*)pActhi, (const __half*)pActlo,
        (const __half*)pW34hi, b3, b4, out);
}